// round 8
// baseline (speedup 1.0000x reference)
#include <cuda_runtime.h>

// EquivariantLayerNorm: dim=1184 = 256(l=0) + 384(l=1) + 320(l=2) + 224(l=3)
// float4 chunk k holds vec indices [32k, 32k+32):
//   k=0,1 -> g0 | k=2,3,4 -> g1 | k=5,6 -> g2 | k=7 -> g2 (lane<16)/g3 | k=8,9 -> g3
// Structural index facts (deterministic _build_indices for these IRREPS):
//   scalar_indices = [0..255];  irrep_idx(f) = f                    (f < 256)
//                               = 256 + (f-256)/3                   (256 <= f < 640)
//                               = 384 + (f-640)/5                   (640 <= f < 960)
//                               = 448 + (f-960)/7                   (960 <= f < 1184)
#define DIM   1184
#define VECS  296
#define EPSV  1e-5f
#define WPB   16     // warps per block (512 threads)

__device__ __forceinline__ float w_of(const float* __restrict__ weight, int f) {
    unsigned idx;
    if (f < 640)      idx = 256u + (unsigned)(f - 256) / 3u;
    else if (f < 960) idx = 384u + (unsigned)(f - 640) / 5u;
    else              idx = 448u + (unsigned)(f - 960) / 7u;
    return __ldg(weight + idx);
}

template <bool GUARD>
__global__ __launch_bounds__(32 * WPB)
void eln_kernel(const float4* __restrict__ x, float4* __restrict__ out,
                const float* __restrict__ weight,
                const float* __restrict__ bias, int n_rows) {
    const int lane = threadIdx.x & 31;
    const int warp = threadIdx.x >> 5;
    const int row  = blockIdx.x * WPB + warp;
    if (GUARD && row >= n_rows) return;

    const float4* __restrict__ xr  = x   + (size_t)row * VECS;
    float4*       __restrict__ orw = out + (size_t)row * VECS;

    // ---- front-batched coalesced streaming loads: whole row in registers ----
    float4 v[10];
    #pragma unroll
    for (int k = 0; k < 9; k++) v[k] = __ldcs(xr + lane + 32 * k);
    const bool has9 = (lane < 8);
    v[9] = make_float4(0.f, 0.f, 0.f, 0.f);
    if (has9) v[9] = __ldcs(xr + lane + 288);

    // ---- per-lane stats, compile-time group routing ----
    float ssum = 0.f, q0 = 0.f, q1 = 0.f, q2 = 0.f, q3 = 0.f;
    #pragma unroll
    for (int k = 0; k < 10; k++) {
        float d = fmaf(v[k].x, v[k].x, fmaf(v[k].y, v[k].y,
                  fmaf(v[k].z, v[k].z, v[k].w * v[k].w)));
        if (k < 2)       { ssum += v[k].x + v[k].y + v[k].z + v[k].w; q0 += d; }
        else if (k < 5)  q1 += d;
        else if (k < 7)  q2 += d;
        else if (k == 7) { if (lane < 16) q2 += d; else q3 += d; }
        else             q3 += d;
    }

    const float4* __restrict__ w4 = (const float4*)weight;  // identity map for f<256
    const float4* __restrict__ b4 = (const float4*)bias;

    // ---- stage 1: reduce scalar-group stats only, store chunks 0-1 early ----
    #pragma unroll
    for (int o = 16; o; o >>= 1) {
        ssum += __shfl_xor_sync(0xffffffffu, ssum, o);
        q0   += __shfl_xor_sync(0xffffffffu, q0,   o);
    }
    const float m  = ssum * (1.0f / 256.0f);
    const float r0 = rsqrtf(q0 * (1.0f / 256.0f) - m * m + EPSV);

    #pragma unroll
    for (int k = 0; k < 2; k++) {
        const int vi = lane + 32 * k;
        float4 w = __ldg(w4 + vi), b = __ldg(b4 + vi), o;
        o.x = fmaf((v[k].x - m) * r0, w.x, b.x);
        o.y = fmaf((v[k].y - m) * r0, w.y, b.y);
        o.z = fmaf((v[k].z - m) * r0, w.z, b.z);
        o.w = fmaf((v[k].w - m) * r0, w.w, b.w);
        __stcs(orw + vi, o);
    }

    // ---- stage 2: reduce remaining group stats, store chunks 2-9 ----
    #pragma unroll
    for (int o = 16; o; o >>= 1) {
        q1 += __shfl_xor_sync(0xffffffffu, q1, o);
        q2 += __shfl_xor_sync(0xffffffffu, q2, o);
        q3 += __shfl_xor_sync(0xffffffffu, q3, o);
    }
    const float r1 = rsqrtf(q1 * (1.0f / 384.0f) + EPSV);
    const float r2 = rsqrtf(q2 * (1.0f / 320.0f) + EPSV);
    const float r3 = rsqrtf(q3 * (1.0f / 224.0f) + EPSV);
    const float r23 = (lane < 16) ? r2 : r3;   // chunk-7 per-lane norm

    #pragma unroll
    for (int k = 2; k < 10; k++) {
        if (k < 9 || has9) {
            const int vi = lane + 32 * k;
            const float rg = (k < 5) ? r1 : (k < 7) ? r2 : (k == 7) ? r23 : r3;
            const int f = vi * 4;
            float4 o;
            o.x = v[k].x * rg * w_of(weight, f + 0);
            o.y = v[k].y * rg * w_of(weight, f + 1);
            o.z = v[k].z * rg * w_of(weight, f + 2);
            o.w = v[k].w * rg * w_of(weight, f + 3);
            __stcs(orw + vi, o);
        }
    }
}

extern "C" void kernel_launch(void* const* d_in, const int* in_sizes, int n_in,
                              void* d_out, int out_size) {
    const float* x      = (const float*)d_in[0];
    const float* weight = (const float*)d_in[1];
    const float* bias   = (const float*)d_in[2];
    // d_in[3..6] = group_idx / irrep_idx / scalar_indices / scalar_group
    //   (structure compile-time known; see header comment)
    float* out = (float*)d_out;

    const int n_rows = in_sizes[0] / DIM;

    if ((n_rows % WPB) == 0) {
        eln_kernel<false><<<n_rows / WPB, 32 * WPB>>>((const float4*)x, (float4*)out,
                                                      weight, bias, n_rows);
    } else {
        eln_kernel<true><<<(n_rows + WPB - 1) / WPB, 32 * WPB>>>((const float4*)x, (float4*)out,
                                                                 weight, bias, n_rows);
    }
}

// round 9
// speedup vs baseline: 1.0107x; 1.0107x over previous
#include <cuda_runtime.h>

// EquivariantLayerNorm: dim=1184 = 256(l=0) + 384(l=1) + 320(l=2) + 224(l=3)
// float4 chunk k holds vec indices [32k, 32k+32):
//   k=0,1 -> g0 | k=2,3,4 -> g1 | k=5,6 -> g2 | k=7 -> g2 (lane<16)/g3 | k=8,9 -> g3
// Structural index facts (deterministic _build_indices for these IRREPS):
//   scalar_indices = [0..255];  irrep_idx(f) = f                    (f < 256)
//                               = 256 + (f-256)/3                   (256 <= f < 640)
//                               = 384 + (f-640)/5                   (640 <= f < 960)
//                               = 448 + (f-960)/7                   (960 <= f < 1184)
#define DIM   1184
#define VECS  296
#define EPSV  1e-5f
#define WPB   8      // warps per block (256 threads) — proven best config

__device__ __forceinline__ float w_of(const float* __restrict__ weight, int f) {
    unsigned idx;
    if (f < 640)      idx = 256u + (unsigned)(f - 256) / 3u;
    else if (f < 960) idx = 384u + (unsigned)(f - 640) / 5u;
    else              idx = 448u + (unsigned)(f - 960) / 7u;
    return __ldg(weight + idx);
}

template <bool GUARD>
__global__ __launch_bounds__(32 * WPB)
void eln_kernel(const float4* __restrict__ x, float4* __restrict__ out,
                const float* __restrict__ weight,
                const float* __restrict__ bias, int n_rows) {
    const int lane = threadIdx.x & 31;
    const int warp = threadIdx.x >> 5;
    const int row  = blockIdx.x * WPB + warp;
    if (GUARD && row >= n_rows) return;

    const float4* __restrict__ xr  = x   + (size_t)row * VECS;
    float4*       __restrict__ orw = out + (size_t)row * VECS;

    // ---- front-batched coalesced streaming loads: whole row in registers ----
    float4 v[10];
    #pragma unroll
    for (int k = 0; k < 9; k++) v[k] = __ldcs(xr + lane + 32 * k);
    const bool has9 = (lane < 8);
    v[9] = make_float4(0.f, 0.f, 0.f, 0.f);
    if (has9) v[9] = __ldcs(xr + lane + 288);

    // ---- per-lane stats, compile-time group routing ----
    float ssum = 0.f, q0 = 0.f, q1 = 0.f, q2 = 0.f, q3 = 0.f;
    #pragma unroll
    for (int k = 0; k < 10; k++) {
        float d = fmaf(v[k].x, v[k].x, fmaf(v[k].y, v[k].y,
                  fmaf(v[k].z, v[k].z, v[k].w * v[k].w)));
        if (k < 2)       { ssum += v[k].x + v[k].y + v[k].z + v[k].w; q0 += d; }
        else if (k < 5)  q1 += d;
        else if (k < 7)  q2 += d;
        else if (k == 7) { if (lane < 16) q2 += d; else q3 += d; }
        else             q3 += d;
    }

    const float4* __restrict__ w4 = (const float4*)weight;  // identity map for f<256
    const float4* __restrict__ b4 = (const float4*)bias;

    // ---- stage 1: reduce scalar-group stats only, store chunks 0-1 early ----
    #pragma unroll
    for (int o = 16; o; o >>= 1) {
        ssum += __shfl_xor_sync(0xffffffffu, ssum, o);
        q0   += __shfl_xor_sync(0xffffffffu, q0,   o);
    }
    const float m  = ssum * (1.0f / 256.0f);
    const float r0 = rsqrtf(q0 * (1.0f / 256.0f) - m * m + EPSV);

    #pragma unroll
    for (int k = 0; k < 2; k++) {
        const int vi = lane + 32 * k;
        float4 w = __ldg(w4 + vi), b = __ldg(b4 + vi), o;
        o.x = fmaf((v[k].x - m) * r0, w.x, b.x);
        o.y = fmaf((v[k].y - m) * r0, w.y, b.y);
        o.z = fmaf((v[k].z - m) * r0, w.z, b.z);
        o.w = fmaf((v[k].w - m) * r0, w.w, b.w);
        __stcs(orw + vi, o);
    }

    // ---- stage 2: reduce remaining group stats, store chunks 2-9 ----
    #pragma unroll
    for (int o = 16; o; o >>= 1) {
        q1 += __shfl_xor_sync(0xffffffffu, q1, o);
        q2 += __shfl_xor_sync(0xffffffffu, q2, o);
        q3 += __shfl_xor_sync(0xffffffffu, q3, o);
    }
    const float r1 = rsqrtf(q1 * (1.0f / 384.0f) + EPSV);
    const float r2 = rsqrtf(q2 * (1.0f / 320.0f) + EPSV);
    const float r3 = rsqrtf(q3 * (1.0f / 224.0f) + EPSV);
    const float r23 = (lane < 16) ? r2 : r3;   // chunk-7 per-lane norm

    #pragma unroll
    for (int k = 2; k < 10; k++) {
        if (k < 9 || has9) {
            const int vi = lane + 32 * k;
            const float rg = (k < 5) ? r1 : (k < 7) ? r2 : (k == 7) ? r23 : r3;
            const int f = vi * 4;
            float4 o;
            o.x = v[k].x * rg * w_of(weight, f + 0);
            o.y = v[k].y * rg * w_of(weight, f + 1);
            o.z = v[k].z * rg * w_of(weight, f + 2);
            o.w = v[k].w * rg * w_of(weight, f + 3);
            __stcs(orw + vi, o);
        }
    }
}

extern "C" void kernel_launch(void* const* d_in, const int* in_sizes, int n_in,
                              void* d_out, int out_size) {
    const float* x      = (const float*)d_in[0];
    const float* weight = (const float*)d_in[1];
    const float* bias   = (const float*)d_in[2];
    // d_in[3..6] = group_idx / irrep_idx / scalar_indices / scalar_group
    //   (structure compile-time known; see header comment)
    float* out = (float*)d_out;

    const int n_rows = in_sizes[0] / DIM;

    if ((n_rows % WPB) == 0) {
        eln_kernel<false><<<n_rows / WPB, 32 * WPB>>>((const float4*)x, (float4*)out,
                                                      weight, bias, n_rows);
    } else {
        eln_kernel<true><<<(n_rows + WPB - 1) / WPB, 32 * WPB>>>((const float4*)x, (float4*)out,
                                                                 weight, bias, n_rows);
    }
}